// round 2
// baseline (speedup 1.0000x reference)
#include <cuda_runtime.h>
#include <cuda_bf16.h>

#define NN 50000
#define NE 800000
#define HID 64

// ---------------- scratch (device globals; no allocation allowed) -------------
__device__ float g_bufA[NN * HID];   // GEMM output (pre-aggregation)
__device__ float g_bufB[NN * HID];   // aggregation output (post relu)
__device__ float g_z[NN];            // final-layer pre-aggregation scalar
__device__ float g_dinv[NN];
__device__ int   g_cnt[NN];
__device__ int   g_rowptr[NN + 1];
__device__ int   g_fill[NN];
__device__ int   g_col[NE];          // src per CSR slot (grouped by dst)
__device__ float g_wt[NE];           // dinv[src]*dinv[dst] per CSR slot

// ---------------- CSR build --------------------------------------------------
__global__ void k_zero_cnt() {
    int i = blockIdx.x * blockDim.x + threadIdx.x;
    if (i < NN) g_cnt[i] = 0;
}

__global__ void k_count(const int* __restrict__ ei) {
    int e = blockIdx.x * blockDim.x + threadIdx.x;
    if (e < NE) {
        int d = ei[NE + e];
        atomicAdd(&g_cnt[d], 1);
    }
}

__global__ void k_dinv() {
    int i = blockIdx.x * blockDim.x + threadIdx.x;
    if (i < NN) g_dinv[i] = rsqrtf((float)(g_cnt[i] + 1));  // +1 self loop
}

// single-block exclusive scan of g_cnt -> g_rowptr / g_fill
__global__ void k_scan() {
    __shared__ int sdata[1024];
    __shared__ int carry_s;
    if (threadIdx.x == 0) carry_s = 0;
    __syncthreads();
    for (int base = 0; base < NN; base += 1024) {
        int i = base + threadIdx.x;
        int v = (i < NN) ? g_cnt[i] : 0;
        sdata[threadIdx.x] = v;
        __syncthreads();
        for (int off = 1; off < 1024; off <<= 1) {
            int t = (threadIdx.x >= off) ? sdata[threadIdx.x - off] : 0;
            __syncthreads();
            sdata[threadIdx.x] += t;
            __syncthreads();
        }
        if (i < NN) {
            int excl = carry_s + sdata[threadIdx.x] - v;
            g_rowptr[i] = excl;
            g_fill[i]   = excl;
        }
        __syncthreads();
        if (threadIdx.x == 0) carry_s += sdata[1023];
        __syncthreads();
    }
    if (threadIdx.x == 0) g_rowptr[NN] = carry_s;
}

__global__ void k_scatter(const int* __restrict__ ei) {
    int e = blockIdx.x * blockDim.x + threadIdx.x;
    if (e < NE) {
        int s = ei[e];
        int d = ei[NE + e];
        int pos = atomicAdd(&g_fill[d], 1);
        g_col[pos] = s;
        g_wt[pos]  = g_dinv[s] * g_dinv[d];
    }
}

// ---------------- dense layers ----------------------------------------------
// x[NN,4] @ W_in[4,64] -> bufA
__global__ void k_gemm_in(const float* __restrict__ x, const float* __restrict__ W) {
    __shared__ float Ws[4 * HID];
    if (threadIdx.x < 256) Ws[threadIdx.x] = W[threadIdx.x];
    __syncthreads();
    int t = blockIdx.x * blockDim.x + threadIdx.x;
    int n = t >> 6, f = t & 63;
    if (n < NN) {
        float acc = 0.f;
        #pragma unroll
        for (int k = 0; k < 4; k++) acc = fmaf(x[n * 4 + k], Ws[k * HID + f], acc);
        g_bufA[n * HID + f] = acc;
    }
}

// bufB[NN,64] @ W[64,64] -> bufA   (256 threads, 64 nodes per block)
__global__ void k_gemm64(const float* __restrict__ W) {
    __shared__ float Ws[HID * HID];
    __shared__ float Hs[4 * HID];
    for (int i = threadIdx.x; i < HID * HID; i += blockDim.x) Ws[i] = W[i];
    int nodeBase = blockIdx.x * 64;
    int f  = threadIdx.x & 63;
    int nl = threadIdx.x >> 6;  // 0..3
    for (int c = 0; c < 64; c += 4) {
        __syncthreads();  // also covers initial Ws load
        int n = nodeBase + c + nl;
        Hs[nl * HID + f] = (n < NN) ? g_bufB[n * HID + f] : 0.f;
        __syncthreads();
        if (n < NN) {
            float acc = 0.f;
            #pragma unroll
            for (int k = 0; k < HID; k++) acc = fmaf(Hs[nl * HID + k], Ws[k * HID + f], acc);
            g_bufA[n * HID + f] = acc;
        }
    }
}

// bufB[NN,64] @ W_out[64,1] -> g_z  (warp per node)
__global__ void k_gemm_out(const float* __restrict__ Wout) {
    int warp = (blockIdx.x * blockDim.x + threadIdx.x) >> 5;
    int lane = threadIdx.x & 31;
    if (warp < NN) {
        float a = g_bufB[warp * HID + lane] * Wout[lane]
                + g_bufB[warp * HID + lane + 32] * Wout[lane + 32];
        #pragma unroll
        for (int o = 16; o; o >>= 1) a += __shfl_xor_sync(0xffffffffu, a, o);
        if (lane == 0) g_z[warp] = a;
    }
}

// ---------------- aggregation -----------------------------------------------
// out[n,:] = relu?( sum_e w_e * bufA[src_e,:] + dinv[n]^2*bufA[n,:] + bias )
__global__ void k_agg64(const float* __restrict__ bias, int relu) {
    int warp = (blockIdx.x * blockDim.x + threadIdx.x) >> 5;
    int lane = threadIdx.x & 31;
    if (warp >= NN) return;
    int n = warp;
    float a0 = 0.f, a1 = 0.f;
    int beg = g_rowptr[n], end = g_rowptr[n + 1];
    for (int j = beg; j < end; j++) {
        int s = g_col[j];
        float w = g_wt[j];
        a0 = fmaf(w, __ldg(&g_bufA[s * HID + lane]), a0);
        a1 = fmaf(w, __ldg(&g_bufA[s * HID + lane + 32]), a1);
    }
    float di = g_dinv[n], ws = di * di;
    a0 = fmaf(ws, g_bufA[n * HID + lane],      a0) + bias[lane];
    a1 = fmaf(ws, g_bufA[n * HID + lane + 32], a1) + bias[lane + 32];
    if (relu) { a0 = fmaxf(a0, 0.f); a1 = fmaxf(a1, 0.f); }
    g_bufB[n * HID + lane]      = a0;
    g_bufB[n * HID + lane + 32] = a1;
}

__global__ void k_agg_scalar(float* __restrict__ out, const float* __restrict__ b_out) {
    int n = blockIdx.x * blockDim.x + threadIdx.x;
    if (n < NN) {
        float acc = 0.f;
        int beg = g_rowptr[n], end = g_rowptr[n + 1];
        for (int j = beg; j < end; j++) acc = fmaf(g_wt[j], __ldg(&g_z[g_col[j]]), acc);
        float di = g_dinv[n];
        acc = fmaf(di * di, g_z[n], acc);
        out[n] = acc + b_out[0];
    }
}

// ---------------- launch ------------------------------------------------------
extern "C" void kernel_launch(void* const* d_in, const int* in_sizes, int n_in,
                              void* d_out, int out_size) {
    const float* x     = (const float*)d_in[0];
    const int*   ei    = (const int*)d_in[1];
    const float* W_in  = (const float*)d_in[2];
    const float* b_in  = (const float*)d_in[3];
    const float* W_h   = (const float*)d_in[4];
    const float* b_h   = (const float*)d_in[5];
    const float* W_out = (const float*)d_in[6];
    const float* b_out = (const float*)d_in[7];
    float*       out   = (float*)d_out;

    const int TB = 256;
    const int gN  = (NN + TB - 1) / TB;
    const int gE  = (NE + TB - 1) / TB;
    const int gNF = (NN * HID + TB - 1) / TB;          // thread per (n,f)
    const int gW  = (NN * 32 + TB - 1) / TB;           // warp per node
    const int gG  = (NN + 63) / 64;                    // gemm64 blocks

    // CSR build
    k_zero_cnt<<<gN, TB>>>();
    k_count<<<gE, TB>>>(ei);
    k_dinv<<<gN, TB>>>();
    k_scan<<<1, 1024>>>();
    k_scatter<<<gE, TB>>>(ei);

    // layer 0: x @ W_in -> bufA ; aggregate -> bufB (relu)
    k_gemm_in<<<gNF, TB>>>(x, W_in);
    k_agg64<<<gW, TB>>>(b_in, 1);

    // hidden layers
    for (int l = 0; l < 3; l++) {
        k_gemm64<<<gG, TB>>>(W_h + l * HID * HID);
        k_agg64<<<gW, TB>>>(b_h + l * HID, 1);
    }

    // output layer
    k_gemm_out<<<gW, TB>>>(W_out);
    k_agg_scalar<<<gN, TB>>>(out, b_out);
}